// round 13
// baseline (speedup 1.0000x reference)
#include <cuda_runtime.h>
#include <cuda_bf16.h>
#include <cstdint>

// Inputs (metadata order):
//   d_in[0]: output  float32  [16, 512, 32000]  (B*S = 8192 rows, V = 32000)
//   d_in[1]: target  int32    [16, 512]
// Output: scalar float32 = sum(target!=0 ? -log(p_target) : 0) / count(target!=0)
//
// FINAL kernel. Floor-confirmed ~6.6us wall across 5 structural variants;
// ~5us of that is fixed graph-replay/launch overhead, the rest is the
// irreducible 2-deep dependent-load chain (target -> gather).
//
//   32 blocks x 32 threads (one warp per block), 8 rows per thread.
//   int4 target loads -> 8 independent gathers (MLP=8, one L2 latency)
//   -> warp shuffle tree -> ONE packed u64 atomicAdd per block:
//     bits[58:63] arrival counter (+1<<58 per block)
//     bits[14:57] sum, fixed-point scale 2^24  (total < 2^41)
//     bits[ 0:13] count                         (total <= 8192)
//   Integer adds are order-independent -> bitwise deterministic; the
//   atomic's return value lets the last-arriving block finalize with no
//   memory reads. g_acc reset by finalizer -> graph-replay safe.

#define ROWS     8192
#define VOCAB    32000
#define NBLOCKS  32
#define NTHREADS 32
#define RPT      8            // rows per thread

#define CTR_ONE   (1ULL << 58)
#define SUM_SHIFT 14
#define CNT_MASK  ((1ULL << SUM_SHIFT) - 1ULL)
#define SUM_MASK  ((1ULL << 58) - 1ULL)
#define FP_SCALE  16777216.0f          // 2^24

__device__ unsigned long long g_acc;   // zero-init; finalizer resets

__global__ __launch_bounds__(NTHREADS, 1)
void nll_gather_kernel(const float* __restrict__ out_probs,
                       const int* __restrict__ target,
                       float* __restrict__ result)
{
    const int lane = threadIdx.x;
    const int base_row = blockIdx.x * (NTHREADS * RPT) + lane * RPT;

    // 2x int4 = 8 consecutive targets per thread; warp covers 1KB contiguous.
    const int4* tv = (const int4*)(target + base_row);
    int4 t0 = __ldg(&tv[0]);
    int4 t1 = __ldg(&tv[1]);
    int t[RPT] = {t0.x, t0.y, t0.z, t0.w, t1.x, t1.y, t1.z, t1.w};

    // 8 independent gathers back-to-back (MLP=8, ~1 L2 latency total).
    float p[RPT];
    #pragma unroll
    for (int r = 0; r < RPT; ++r)
        p[r] = __ldcg(&out_probs[(size_t)(base_row + r) * VOCAB + t[r]]);

    float lsum = 0.0f;
    int   lcnt = 0;
    #pragma unroll
    for (int r = 0; r < RPT; ++r) {
        if (t[r] != 0) {
            lsum += -__logf(p[r]);
            lcnt += 1;
        }
    }

    // Single warp shuffle tree.
    #pragma unroll
    for (int off = 16; off > 0; off >>= 1) {
        lsum += __shfl_down_sync(0xFFFFFFFFu, lsum, off);
        lcnt += __shfl_down_sync(0xFFFFFFFFu, lcnt, off);
    }

    if (lane == 0) {
        unsigned long long fx =
            (unsigned long long)(lsum * FP_SCALE + 0.5f);   // < 2^38 per block
        unsigned long long pk =
            CTR_ONE | (fx << SUM_SHIFT) | (unsigned long long)lcnt;

        unsigned long long old = atomicAdd(&g_acc, pk);

        if ((old >> 58) == NBLOCKS - 1) {
            // Last arriver already holds the full total: no loads needed.
            unsigned long long tot = old + pk;
            float sum = (float)((tot & SUM_MASK) >> SUM_SHIFT) *
                        (1.0f / FP_SCALE);
            float cnt = (float)(tot & CNT_MASK);
            result[0] = sum / cnt;
            g_acc = 0ULL;   // reset for next graph replay
        }
    }
}

extern "C" void kernel_launch(void* const* d_in, const int* in_sizes, int n_in,
                              void* d_out, int out_size)
{
    const float* probs  = (const float*)d_in[0];
    const int*   target = (const int*)d_in[1];
    float*       result = (float*)d_out;

    nll_gather_kernel<<<NBLOCKS, NTHREADS>>>(probs, target, result);
}

// round 14
// speedup vs baseline: 1.0437x; 1.0437x over previous
#include <cuda_runtime.h>
#include <cuda_bf16.h>
#include <cstdint>

// Inputs (metadata order):
//   d_in[0]: output  float32  [16, 512, 32000]  (B*S = 8192 rows, V = 32000)
//   d_in[1]: target  int32    [16, 512]
// Output: scalar float32 = sum(target!=0 ? -log(p_target) : 0) / count(target!=0)
//
// FINAL kernel. 7 runs across 5 structural variants all land in
// [6.62, 6.91] us; identical source measured 6.656 and 6.880 on consecutive
// runs, so the band is run-to-run noise. ~5us is fixed graph-replay/launch
// overhead; the rest is the irreducible 2-deep dependent-load chain
// (target load -> data-dependent gather).
//
//   32 blocks x 32 threads (one warp per block), 8 rows per thread.
//   int4 target loads -> 8 independent gathers (MLP=8, one L2 latency)
//   -> warp shuffle tree -> ONE packed u64 atomicAdd per block:
//     bits[58:63] arrival counter (+1<<58 per block)
//     bits[14:57] sum, fixed-point scale 2^24  (total < 2^41)
//     bits[ 0:13] count                         (total <= 8192)
//   Integer adds are order-independent -> bitwise deterministic; the
//   atomic's return value lets the last-arriving block finalize with no
//   memory reads. g_acc reset by finalizer -> graph-replay safe.

#define ROWS     8192
#define VOCAB    32000
#define NBLOCKS  32
#define NTHREADS 32
#define RPT      8            // rows per thread

#define CTR_ONE   (1ULL << 58)
#define SUM_SHIFT 14
#define CNT_MASK  ((1ULL << SUM_SHIFT) - 1ULL)
#define SUM_MASK  ((1ULL << 58) - 1ULL)
#define FP_SCALE  16777216.0f          // 2^24

__device__ unsigned long long g_acc;   // zero-init; finalizer resets

__global__ __launch_bounds__(NTHREADS, 1)
void nll_gather_kernel(const float* __restrict__ out_probs,
                       const int* __restrict__ target,
                       float* __restrict__ result)
{
    const int lane = threadIdx.x;
    const int base_row = blockIdx.x * (NTHREADS * RPT) + lane * RPT;

    // 2x int4 = 8 consecutive targets per thread; warp covers 1KB contiguous.
    const int4* tv = (const int4*)(target + base_row);
    int4 t0 = __ldg(&tv[0]);
    int4 t1 = __ldg(&tv[1]);
    int t[RPT] = {t0.x, t0.y, t0.z, t0.w, t1.x, t1.y, t1.z, t1.w};

    // 8 independent gathers back-to-back (MLP=8, ~1 L2 latency total).
    float p[RPT];
    #pragma unroll
    for (int r = 0; r < RPT; ++r)
        p[r] = __ldcg(&out_probs[(size_t)(base_row + r) * VOCAB + t[r]]);

    float lsum = 0.0f;
    int   lcnt = 0;
    #pragma unroll
    for (int r = 0; r < RPT; ++r) {
        if (t[r] != 0) {
            lsum += -__logf(p[r]);
            lcnt += 1;
        }
    }

    // Single warp shuffle tree.
    #pragma unroll
    for (int off = 16; off > 0; off >>= 1) {
        lsum += __shfl_down_sync(0xFFFFFFFFu, lsum, off);
        lcnt += __shfl_down_sync(0xFFFFFFFFu, lcnt, off);
    }

    if (lane == 0) {
        unsigned long long fx =
            (unsigned long long)(lsum * FP_SCALE + 0.5f);   // < 2^38 per block
        unsigned long long pk =
            CTR_ONE | (fx << SUM_SHIFT) | (unsigned long long)lcnt;

        unsigned long long old = atomicAdd(&g_acc, pk);

        if ((old >> 58) == NBLOCKS - 1) {
            // Last arriver already holds the full total: no loads needed.
            unsigned long long tot = old + pk;
            float sum = (float)((tot & SUM_MASK) >> SUM_SHIFT) *
                        (1.0f / FP_SCALE);
            float cnt = (float)(tot & CNT_MASK);
            result[0] = sum / cnt;
            g_acc = 0ULL;   // reset for next graph replay
        }
    }
}

extern "C" void kernel_launch(void* const* d_in, const int* in_sizes, int n_in,
                              void* d_out, int out_size)
{
    const float* probs  = (const float*)d_in[0];
    const int*   target = (const int*)d_in[1];
    float*       result = (float*)d_out;

    nll_gather_kernel<<<NBLOCKS, NTHREADS>>>(probs, target, result);
}